// round 10
// baseline (speedup 1.0000x reference)
#include <cuda_runtime.h>
#include <math.h>

static constexpr int BB = 8;
static constexpr int TT = 2048;
static constexpr int CC = 1024;
static constexpr int HSd = 64;

// fp32 scratch for q,k,v  (12 MB total; __device__ globals, no allocation)
__device__ float g_q[BB * TT * HSd];
__device__ float g_k[BB * TT * HSd];
__device__ float g_v[BB * TT * HSd];

// ---------------------------------------------------------------------------
// Kernel 1: fused QKV projection.
// Grid: (B*T/64) blocks, 256 threads. Each block computes a 64-row tile of
// q|k|v (64 x 192 output) via smem-tiled GEMM over C=1024.
// Thread map: rg = tid>>4 owns rows r0..r0+3, cg = tid&15 owns cols cg+16*j.
// ---------------------------------------------------------------------------
__global__ __launch_bounds__(256) void proj_kernel(
    const float* __restrict__ x,
    const float* __restrict__ Wq,
    const float* __restrict__ Wk,
    const float* __restrict__ Wv)
{
    extern __shared__ float sm[];
    float* xs = sm;              // 64 x 65 (padded)
    float* ws = sm + 64 * 65;    // 64 x 192

    const int tid = threadIdx.x;
    const int rg  = tid >> 4;    // 0..15
    const int cg  = tid & 15;    // 0..15
    const int r0  = rg * 4;
    const int row0 = blockIdx.x * 64;   // flattened (b,t) row

    float acc[4][12];
#pragma unroll
    for (int i = 0; i < 4; i++)
#pragma unroll
        for (int j = 0; j < 12; j++) acc[i][j] = 0.f;

    for (int kc = 0; kc < CC / 64; kc++) {
        __syncthreads();
        // load x tile: 64 rows x 64 k
#pragma unroll
        for (int l = 0; l < 16; l++) {
            int e = l * 256 + tid;
            int r = e >> 6, c = e & 63;
            xs[r * 65 + c] = x[(row0 + r) * CC + kc * 64 + c];
        }
        // load fused W tile: 64 k x 192 cols (q|k|v)
#pragma unroll
        for (int l = 0; l < 48; l++) {
            int e  = l * 256 + tid;
            int kk = e / 192, c = e % 192;
            int k  = kc * 64 + kk;
            float w;
            if (c < 64)       w = Wq[k * HSd + c];
            else if (c < 128) w = Wk[k * HSd + (c - 64)];
            else              w = Wv[k * HSd + (c - 128)];
            ws[kk * 192 + c] = w;
        }
        __syncthreads();

#pragma unroll 8
        for (int kk = 0; kk < 64; kk++) {
            float a[4], w[12];
#pragma unroll
            for (int i = 0; i < 4; i++) a[i] = xs[(r0 + i) * 65 + kk];
#pragma unroll
            for (int j = 0; j < 12; j++) w[j] = ws[kk * 192 + cg + 16 * j];
#pragma unroll
            for (int i = 0; i < 4; i++)
#pragma unroll
                for (int j = 0; j < 12; j++)
                    acc[i][j] = fmaf(a[i], w[j], acc[i][j]);
        }
    }

    // scatter to q/k/v scratch
#pragma unroll
    for (int i = 0; i < 4; i++) {
        int row = row0 + r0 + i;
#pragma unroll
        for (int j = 0; j < 12; j++) {
            int c = cg + 16 * j;
            float* dst = (c < 64) ? g_q : ((c < 128) ? g_k : g_v);
            dst[row * HSd + (c & 63)] = acc[i][j];
        }
    }
}

// ---------------------------------------------------------------------------
// Kernel 2: causal flash attention over the fp32 scratch.
// Grid: (T/64, B) blocks, 256 threads. Q tile = 64 rows; KV tiles 0..qt.
// Thread map: rg owns rows r0..r0+3; cg owns score/output cols cg+16*j.
// Online softmax with width-16 shuffle reductions (a row group = 16
// consecutive lanes = half a warp).
// ---------------------------------------------------------------------------
__global__ __launch_bounds__(256) void attn_kernel(float* __restrict__ out)
{
    extern __shared__ float sm[];
    float* Qs = sm;                  // 64 x 64
    float* Ks = Qs + 64 * 64;        // 64 x 65 (padded)
    float* Vs = Ks + 64 * 65;        // 64 x 64
    float* Ps = Vs + 64 * 64;        // 64 x 64

    const int tid = threadIdx.x;
    const int rg  = tid >> 4, cg = tid & 15;
    const int r0  = rg * 4;
    const int b   = blockIdx.y;
    const int qt  = blockIdx.x;
    const int qr0 = qt * 64;
    const int base = b * TT * HSd;

    // load Q tile
#pragma unroll
    for (int l = 0; l < 16; l++) {
        int e = l * 256 + tid;
        int r = e >> 6, h = e & 63;
        Qs[r * 64 + h] = g_q[base + (qr0 + r) * HSd + h];
    }

    float acc[4][4];
    float m_i[4], l_i[4];
#pragma unroll
    for (int i = 0; i < 4; i++) {
        m_i[i] = -1e30f; l_i[i] = 0.f;
#pragma unroll
        for (int j = 0; j < 4; j++) acc[i][j] = 0.f;
    }

    for (int kt = 0; kt <= qt; kt++) {
        const int kc0 = kt * 64;
        __syncthreads();   // protect Ks/Vs (prev GEMM done) before overwrite
#pragma unroll
        for (int l = 0; l < 16; l++) {
            int e = l * 256 + tid;
            int r = e >> 6, h = e & 63;
            Ks[r * 65 + h] = g_k[base + (kc0 + r) * HSd + h];
            Vs[r * 64 + h] = g_v[base + (kc0 + r) * HSd + h];
        }
        __syncthreads();

        // S = Q K^T  (4x4 per thread)
        float s[4][4];
#pragma unroll
        for (int i = 0; i < 4; i++)
#pragma unroll
            for (int j = 0; j < 4; j++) s[i][j] = 0.f;

#pragma unroll 8
        for (int h = 0; h < 64; h++) {
            float qv[4], kv[4];
#pragma unroll
            for (int i = 0; i < 4; i++) qv[i] = Qs[(r0 + i) * 64 + h];
#pragma unroll
            for (int j = 0; j < 4; j++) kv[j] = Ks[(cg + 16 * j) * 65 + h];
#pragma unroll
            for (int i = 0; i < 4; i++)
#pragma unroll
                for (int j = 0; j < 4; j++)
                    s[i][j] = fmaf(qv[i], kv[j], s[i][j]);
        }

        // scale (C^-0.5 = 1/32) + causal mask (only diagonal tile)
        const bool diag = (kt == qt);
#pragma unroll
        for (int i = 0; i < 4; i++)
#pragma unroll
            for (int j = 0; j < 4; j++) {
                float v = s[i][j] * 0.03125f;
                if (diag && (cg + 16 * j > r0 + i)) v = -1e30f;
                s[i][j] = v;
            }

        // online softmax update
#pragma unroll
        for (int i = 0; i < 4; i++) {
            float mx = fmaxf(fmaxf(s[i][0], s[i][1]), fmaxf(s[i][2], s[i][3]));
#pragma unroll
            for (int off = 8; off > 0; off >>= 1)
                mx = fmaxf(mx, __shfl_xor_sync(0xffffffffu, mx, off, 16));
            float mn   = fmaxf(m_i[i], mx);
            float corr = __expf(m_i[i] - mn);
            m_i[i] = mn;
            float rs = 0.f;
#pragma unroll
            for (int j = 0; j < 4; j++) {
                float p = __expf(s[i][j] - mn);
                s[i][j] = p;
                rs += p;
            }
#pragma unroll
            for (int off = 8; off > 0; off >>= 1)
                rs += __shfl_xor_sync(0xffffffffu, rs, off, 16);
            l_i[i] = l_i[i] * corr + rs;
#pragma unroll
            for (int j = 0; j < 4; j++) acc[i][j] *= corr;
        }

        // stage P for the P @ V GEMM
#pragma unroll
        for (int i = 0; i < 4; i++)
#pragma unroll
            for (int j = 0; j < 4; j++)
                Ps[(r0 + i) * 64 + cg + 16 * j] = s[i][j];
        __syncthreads();

        // O += P V   (4 rows x 4 h-cols per thread)
#pragma unroll 8
        for (int c = 0; c < 64; c++) {
            float pv[4], vv[4];
#pragma unroll
            for (int i = 0; i < 4; i++) pv[i] = Ps[(r0 + i) * 64 + c];
#pragma unroll
            for (int j = 0; j < 4; j++) vv[j] = Vs[c * 64 + cg + 16 * j];
#pragma unroll
            for (int i = 0; i < 4; i++)
#pragma unroll
                for (int j = 0; j < 4; j++)
                    acc[i][j] = fmaf(pv[i], vv[j], acc[i][j]);
        }
    }

    // epilogue: normalize and store
#pragma unroll
    for (int i = 0; i < 4; i++) {
        float inv = 1.0f / l_i[i];
#pragma unroll
        for (int j = 0; j < 4; j++)
            out[base + (qr0 + r0 + i) * HSd + cg + 16 * j] = acc[i][j] * inv;
    }
}

// ---------------------------------------------------------------------------
// Launch. Inputs (metadata order): x, mask, Wq, Wk, Wv. mask is tril(T,T) and
// is applied analytically in-kernel (diagonal-tile predicate), so unused here.
// ---------------------------------------------------------------------------
extern "C" void kernel_launch(void* const* d_in, const int* in_sizes, int n_in,
                              void* d_out, int out_size)
{
    const float* x  = (const float*)d_in[0];
    const float* Wq = (const float*)d_in[2];
    const float* Wk = (const float*)d_in[3];
    const float* Wv = (const float*)d_in[4];
    float* out = (float*)d_out;

    const int PROJ_SMEM = (64 * 65 + 64 * 192) * (int)sizeof(float); // 65792 B
    const int ATTN_SMEM = (64 * 64 * 3 + 64 * 65) * (int)sizeof(float); // 65792 B

    static bool attr_set = false;
    if (!attr_set) {
        cudaFuncSetAttribute(proj_kernel,
                             cudaFuncAttributeMaxDynamicSharedMemorySize, PROJ_SMEM);
        cudaFuncSetAttribute(attn_kernel,
                             cudaFuncAttributeMaxDynamicSharedMemorySize, ATTN_SMEM);
        attr_set = true;
    }

    proj_kernel<<<(BB * TT) / 64, 256, PROJ_SMEM>>>(x, Wq, Wk, Wv);
    attn_kernel<<<dim3(TT / 64, BB), 256, ATTN_SMEM>>>(out);
}

// round 12
// speedup vs baseline: 4.5788x; 4.5788x over previous
#include <cuda_runtime.h>
#include <cstdint>
#include <math.h>

static constexpr int BB = 8;
static constexpr int TT = 2048;
static constexpr int CC = 1024;
static constexpr int HSd = 64;

// fp32 scratch for q,k,v (12 MB; __device__ globals, no allocation)
__device__ float g_q[BB * TT * HSd];
__device__ float g_k[BB * TT * HSd];
__device__ float g_v[BB * TT * HSd];

__device__ __forceinline__ float to_tf32(float x) {
    float r;
    asm("cvt.rna.tf32.f32 %0, %1;" : "=f"(r) : "f"(x));
    return r;
}

// mma.sync m16n8k8 tf32: D += A(16x8,row) * B(8x8,col). D/C in-place.
__device__ __forceinline__ void mma_t(float* d, const uint32_t* a,
                                      uint32_t b0, uint32_t b1) {
    asm volatile(
        "mma.sync.aligned.m16n8k8.row.col.f32.tf32.tf32.f32 "
        "{%0,%1,%2,%3}, {%4,%5,%6,%7}, {%8,%9}, {%0,%1,%2,%3};"
        : "+f"(d[0]), "+f"(d[1]), "+f"(d[2]), "+f"(d[3])
        : "r"(a[0]), "r"(a[1]), "r"(a[2]), "r"(a[3]), "r"(b0), "r"(b1));
}

// ===========================================================================
// Kernel 1: fused QKV projection on mma.sync tf32.
// CTA: 128 rows x 192 cols, K=1024 tiled at 32. 256 thr = 8 warps (4M x 2N),
// warp tile 32x96 (2 m16 x 12 n8). Reg-prefetch double buffering.
// Smem strides: A=36 floats (frag bank = 4r+c, conflict-free),
//               B=200 floats (frag bank = 8k+n, conflict-free).
// ===========================================================================
static constexpr int XS_STRIDE = 36;    // floats
static constexpr int WS_STRIDE = 200;   // floats
static constexpr int XS_ELEMS  = 128 * XS_STRIDE;  // per buffer
static constexpr int WS_ELEMS  = 32 * WS_STRIDE;
static constexpr int PROJ_SMEM = 2 * (XS_ELEMS + WS_ELEMS) * 4;  // 88064 B

__global__ __launch_bounds__(256, 1) void proj_mma(
    const float* __restrict__ x,
    const float* __restrict__ Wq,
    const float* __restrict__ Wk,
    const float* __restrict__ Wv)
{
    extern __shared__ float sm[];
    float* xs = sm;                       // 2 x 128 x 36
    float* ws = sm + 2 * XS_ELEMS;        // 2 x 32 x 200

    const int tid  = threadIdx.x;
    const int lane = tid & 31;
    const int wid  = tid >> 5;
    const int m0   = (wid & 3) * 32;      // warp M offset
    const int n0   = (wid >> 2) * 96;     // warp N offset
    const int row0 = blockIdx.x * 128;

    const float* Wm[3] = {Wq, Wk, Wv};

    float acc[2][12][4];
#pragma unroll
    for (int i = 0; i < 2; i++)
#pragma unroll
        for (int j = 0; j < 12; j++)
#pragma unroll
            for (int c = 0; c < 4; c++) acc[i][j][c] = 0.f;

    float4 pa[4], pb[6];

    // --- prefetch helpers (inlined manually) ---
    // A: thread covers (row = tid/8 + 32p, quad = tid%8), float4 each.
    // B: flat f = tid*4 + 1024p, kk=f/192, r=f%192, m=r/64, h=r%63.
    const int ar = tid >> 3, aq = tid & 7;

#define LDG_TILE(KT)                                                          \
    do {                                                                      \
        const int kc = (KT) * 32;                                             \
        _Pragma("unroll")                                                     \
        for (int p = 0; p < 4; p++)                                           \
            pa[p] = *(const float4*)&x[(size_t)(row0 + ar + 32 * p) * CC      \
                                       + kc + aq * 4];                        \
        _Pragma("unroll")                                                     \
        for (int p = 0; p < 6; p++) {                                         \
            int f = tid * 4 + 1024 * p;                                       \
            int kk = f / 192, r = f % 192;                                    \
            int mtx = r >> 6, h = r & 63;                                     \
            pb[p] = *(const float4*)&Wm[mtx][(size_t)(kc + kk) * HSd + h];    \
        }                                                                     \
    } while (0)

#define STS_TILE(BUF)                                                         \
    do {                                                                      \
        float* xb = xs + (BUF) * XS_ELEMS;                                    \
        float* wb = ws + (BUF) * WS_ELEMS;                                    \
        _Pragma("unroll")                                                     \
        for (int p = 0; p < 4; p++) {                                         \
            float4 v = pa[p];                                                 \
            v.x = to_tf32(v.x); v.y = to_tf32(v.y);                           \
            v.z = to_tf32(v.z); v.w = to_tf32(v.w);                           \
            *(float4*)&xb[(ar + 32 * p) * XS_STRIDE + aq * 4] = v;            \
        }                                                                     \
        _Pragma("unroll")                                                     \
        for (int p = 0; p < 6; p++) {                                         \
            int f = tid * 4 + 1024 * p;                                       \
            int kk = f / 192, r = f % 192;                                    \
            float4 v = pb[p];                                                 \
            v.x = to_tf32(v.x); v.y = to_tf32(v.y);                           \
            v.z = to_tf32(v.z); v.w = to_tf32(v.w);                           \
            *(float4*)&wb[kk * WS_STRIDE + r] = v;                            \
        }                                                                     \
    } while (0)

    LDG_TILE(0);
    STS_TILE(0);
    __syncthreads();

    for (int kt = 0; kt < 32; kt++) {
        if (kt < 31) LDG_TILE(kt + 1);

        const float* X = xs + (kt & 1) * XS_ELEMS;
        const float* W = ws + (kt & 1) * WS_ELEMS;

#pragma unroll
        for (int k = 0; k < 4; k++) {
            uint32_t a[2][4];
#pragma unroll
            for (int i = 0; i < 2; i++) {
                int r = m0 + i * 16 + (lane >> 2);
                int c = k * 8 + (lane & 3);
                a[i][0] = __float_as_uint(X[r * XS_STRIDE + c]);
                a[i][1] = __float_as_uint(X[(r + 8) * XS_STRIDE + c]);
                a[i][2] = __float_as_uint(X[r * XS_STRIDE + c + 4]);
                a[i][3] = __float_as_uint(X[(r + 8) * XS_STRIDE + c + 4]);
            }
#pragma unroll
            for (int j = 0; j < 12; j++) {
                int kr = k * 8 + (lane & 3);
                int nc = n0 + j * 8 + (lane >> 2);
                uint32_t b0 = __float_as_uint(W[kr * WS_STRIDE + nc]);
                uint32_t b1 = __float_as_uint(W[(kr + 4) * WS_STRIDE + nc]);
                mma_t(acc[0][j], a[0], b0, b1);
                mma_t(acc[1][j], a[1], b0, b1);
            }
        }

        if (kt < 31) STS_TILE((kt + 1) & 1);
        __syncthreads();
    }

    // epilogue: D frag (c0,c1)=(row, 2q),(row, 2q+1); (c2,c3)=row+8
#pragma unroll
    for (int i = 0; i < 2; i++) {
        int row = row0 + m0 + i * 16 + (lane >> 2);
#pragma unroll
        for (int j = 0; j < 12; j++) {
            int n   = n0 + j * 8 + 2 * (lane & 3);
            int mtx = n >> 6, h = n & 63;
            float* dst = (mtx == 0) ? g_q : ((mtx == 1) ? g_k : g_v);
            *(float2*)&dst[(size_t)row * HSd + h] =
                make_float2(acc[i][j][0], acc[i][j][1]);
            *(float2*)&dst[(size_t)(row + 8) * HSd + h] =
                make_float2(acc[i][j][2], acc[i][j][3]);
        }
    }
#undef LDG_TILE
#undef STS_TILE
}

// ===========================================================================
// Kernel 2: causal flash attention on mma.sync tf32.
// CTA: Q-tile 128 rows, KV-tile 64. 8 warps, each owns one m16 row band and
// the full N=64 — softmax reductions are quad-shuffles only (no cross-warp).
// All smem arrays stride 68 floats: every fragment access pattern maps to
// bank (4r + c) with r in 0..7, c in 0..3 -> conflict-free.
// ===========================================================================
static constexpr int AST = 68;  // smem stride (floats)
static constexpr int ATTN_SMEM = (128 + 64 + 64 + 128) * AST * 4;  // 104448 B

__global__ __launch_bounds__(256, 1) void attn_mma(float* __restrict__ out)
{
    extern __shared__ float sm[];
    float* Qs = sm;                    // 128 x 68
    float* Ks = Qs + 128 * AST;        // 64 x 68
    float* Vs = Ks + 64 * AST;         // 64 x 68
    float* Ps = Vs + 64 * AST;         // 128 x 68

    const int tid  = threadIdx.x;
    const int lane = tid & 31;
    const int wid  = tid >> 5;
    const int b    = blockIdx.x;
    const int qtile = (gridDim.y - 1) - blockIdx.y;   // heavy tiles first
    const int qr0  = qtile * 128;
    const size_t base = (size_t)b * TT * HSd;

    // load Q tile (tf32-rounded)
#pragma unroll
    for (int p = 0; p < 8; p++) {
        int f = tid * 4 + 1024 * p;
        int r = f >> 6, c = f & 63;
        float4 v = *(const float4*)&g_q[base + (size_t)(qr0 + r) * HSd + c];
        v.x = to_tf32(v.x); v.y = to_tf32(v.y);
        v.z = to_tf32(v.z); v.w = to_tf32(v.w);
        *(float4*)&Qs[r * AST + c] = v;
    }

    float o[8][4];
    float m0s = -1e30f, m1s = -1e30f, l0s = 0.f, l1s = 0.f;
#pragma unroll
    for (int j = 0; j < 8; j++)
#pragma unroll
        for (int c = 0; c < 4; c++) o[j][c] = 0.f;

    const int rlow = qr0 + wid * 16 + (lane >> 2);  // global row (and +8)
    const int nkt  = qtile * 2 + 2;

    for (int kt = 0; kt < nkt; kt++) {
        __syncthreads();
#pragma unroll
        for (int p = 0; p < 4; p++) {
            int f = tid * 4 + 1024 * p;
            int r = f >> 6, c = f & 63;
            float4 kv = *(const float4*)&g_k[base + (size_t)(kt * 64 + r) * HSd + c];
            kv.x = to_tf32(kv.x); kv.y = to_tf32(kv.y);
            kv.z = to_tf32(kv.z); kv.w = to_tf32(kv.w);
            *(float4*)&Ks[r * AST + c] = kv;
            float4 vv = *(const float4*)&g_v[base + (size_t)(kt * 64 + r) * HSd + c];
            vv.x = to_tf32(vv.x); vv.y = to_tf32(vv.y);
            vv.z = to_tf32(vv.z); vv.w = to_tf32(vv.w);
            *(float4*)&Vs[r * AST + c] = vv;
        }
        __syncthreads();

        // warp-uniform skip of fully-masked KV tiles
        if (kt * 64 > qr0 + wid * 16 + 15) continue;

        // ---- S = Q K^T ----
        float s[8][4];
#pragma unroll
        for (int j = 0; j < 8; j++)
#pragma unroll
            for (int c = 0; c < 4; c++) s[j][c] = 0.f;

#pragma unroll
        for (int k = 0; k < 8; k++) {
            uint32_t a[4];
            int r = wid * 16 + (lane >> 2);
            int c = k * 8 + (lane & 3);
            a[0] = __float_as_uint(Qs[r * AST + c]);
            a[1] = __float_as_uint(Qs[(r + 8) * AST + c]);
            a[2] = __float_as_uint(Qs[r * AST + c + 4]);
            a[3] = __float_as_uint(Qs[(r + 8) * AST + c + 4]);
#pragma unroll
            for (int j = 0; j < 8; j++) {
                int key = j * 8 + (lane >> 2);
                uint32_t b0 = __float_as_uint(Ks[key * AST + c]);
                uint32_t b1 = __float_as_uint(Ks[key * AST + c + 4]);
                mma_t(s[j], a, b0, b1);
            }
        }

        // ---- scale + causal mask ----
#pragma unroll
        for (int j = 0; j < 8; j++) {
            int col = kt * 64 + j * 8 + 2 * (lane & 3);
            s[j][0] = (col     > rlow    ) ? -1e30f : s[j][0] * 0.03125f;
            s[j][1] = (col + 1 > rlow    ) ? -1e30f : s[j][1] * 0.03125f;
            s[j][2] = (col     > rlow + 8) ? -1e30f : s[j][2] * 0.03125f;
            s[j][3] = (col + 1 > rlow + 8) ? -1e30f : s[j][3] * 0.03125f;
        }

        // ---- online softmax (quad reductions) ----
        float mx0 = -1e30f, mx1 = -1e30f;
#pragma unroll
        for (int j = 0; j < 8; j++) {
            mx0 = fmaxf(mx0, fmaxf(s[j][0], s[j][1]));
            mx1 = fmaxf(mx1, fmaxf(s[j][2], s[j][3]));
        }
#pragma unroll
        for (int off = 1; off <= 2; off <<= 1) {
            mx0 = fmaxf(mx0, __shfl_xor_sync(0xffffffffu, mx0, off));
            mx1 = fmaxf(mx1, __shfl_xor_sync(0xffffffffu, mx1, off));
        }
        float mn0 = fmaxf(m0s, mx0), mn1 = fmaxf(m1s, mx1);
        float c0 = __expf(m0s - mn0), c1 = __expf(m1s - mn1);
        m0s = mn0; m1s = mn1;

        float rs0 = 0.f, rs1 = 0.f;
#pragma unroll
        for (int j = 0; j < 8; j++) {
            s[j][0] = __expf(s[j][0] - mn0);
            s[j][1] = __expf(s[j][1] - mn0);
            s[j][2] = __expf(s[j][2] - mn1);
            s[j][3] = __expf(s[j][3] - mn1);
            rs0 += s[j][0] + s[j][1];
            rs1 += s[j][2] + s[j][3];
        }
#pragma unroll
        for (int off = 1; off <= 2; off <<= 1) {
            rs0 += __shfl_xor_sync(0xffffffffu, rs0, off);
            rs1 += __shfl_xor_sync(0xffffffffu, rs1, off);
        }
        l0s = l0s * c0 + rs0;
        l1s = l1s * c1 + rs1;
#pragma unroll
        for (int j = 0; j < 8; j++) {
            o[j][0] *= c0; o[j][1] *= c0;
            o[j][2] *= c1; o[j][3] *= c1;
        }

        // ---- stage P (own rows only -> warp-local ordering) ----
        {
            int r = wid * 16 + (lane >> 2);
            int cc = 2 * (lane & 3);
#pragma unroll
            for (int j = 0; j < 8; j++) {
                *(float2*)&Ps[r * AST + j * 8 + cc] =
                    make_float2(to_tf32(s[j][0]), to_tf32(s[j][1]));
                *(float2*)&Ps[(r + 8) * AST + j * 8 + cc] =
                    make_float2(to_tf32(s[j][2]), to_tf32(s[j][3]));
            }
        }
        __syncwarp();

        // ---- O += P V ----
#pragma unroll
        for (int k = 0; k < 8; k++) {
            uint32_t a[4];
            int r = wid * 16 + (lane >> 2);
            int c = k * 8 + (lane & 3);
            a[0] = __float_as_uint(Ps[r * AST + c]);
            a[1] = __float_as_uint(Ps[(r + 8) * AST + c]);
            a[2] = __float_as_uint(Ps[r * AST + c + 4]);
            a[3] = __float_as_uint(Ps[(r + 8) * AST + c + 4]);
#pragma unroll
            for (int j = 0; j < 8; j++) {
                int sv = k * 8 + (lane & 3);
                int h  = j * 8 + (lane >> 2);
                uint32_t b0 = __float_as_uint(Vs[sv * AST + h]);
                uint32_t b1 = __float_as_uint(Vs[(sv + 4) * AST + h]);
                mma_t(o[j], a, b0, b1);
            }
        }
    }

    // epilogue
    float inv0 = 1.0f / l0s, inv1 = 1.0f / l1s;
#pragma unroll
    for (int j = 0; j < 8; j++) {
        int col = j * 8 + 2 * (lane & 3);
        *(float2*)&out[base + (size_t)rlow * HSd + col] =
            make_float2(o[j][0] * inv0, o[j][1] * inv0);
        *(float2*)&out[base + (size_t)(rlow + 8) * HSd + col] =
            make_float2(o[j][2] * inv1, o[j][3] * inv1);
    }
}

// ===========================================================================
// Launch. Inputs: x, mask, Wq, Wk, Wv (mask applied analytically).
// ===========================================================================
extern "C" void kernel_launch(void* const* d_in, const int* in_sizes, int n_in,
                              void* d_out, int out_size)
{
    const float* x  = (const float*)d_in[0];
    const float* Wq = (const float*)d_in[2];
    const float* Wk = (const float*)d_in[3];
    const float* Wv = (const float*)d_in[4];
    float* out = (float*)d_out;

    static bool attr_set = false;
    if (!attr_set) {
        cudaFuncSetAttribute(proj_mma,
                             cudaFuncAttributeMaxDynamicSharedMemorySize, PROJ_SMEM);
        cudaFuncSetAttribute(attn_mma,
                             cudaFuncAttributeMaxDynamicSharedMemorySize, ATTN_SMEM);
        attr_set = true;
    }

    proj_mma<<<(BB * TT) / 128, 256, PROJ_SMEM>>>(x, Wq, Wk, Wv);
    attn_mma<<<dim3(BB, TT / 128), 256, ATTN_SMEM>>>(out);
}

// round 13
// speedup vs baseline: 4.5924x; 1.0030x over previous
#include <cuda_runtime.h>
#include <cstdint>
#include <math.h>

static constexpr int BB = 8;
static constexpr int TT = 2048;
static constexpr int CC = 1024;
static constexpr int HSd = 64;

// fp32 scratch for q,k,v (12 MB; __device__ globals, no allocation)
__device__ float g_q[BB * TT * HSd];
__device__ float g_k[BB * TT * HSd];
__device__ float g_v[BB * TT * HSd];

__device__ __forceinline__ float to_tf32(float x) {
    float r;
    asm("cvt.rna.tf32.f32 %0, %1;" : "=f"(r) : "f"(x));
    return r;
}

// mma.sync m16n8k8 tf32: D += A(16x8,row) * B(8x8,col). D/C in-place.
__device__ __forceinline__ void mma_t(float* d, const uint32_t* a,
                                      uint32_t b0, uint32_t b1) {
    asm volatile(
        "mma.sync.aligned.m16n8k8.row.col.f32.tf32.tf32.f32 "
        "{%0,%1,%2,%3}, {%4,%5,%6,%7}, {%8,%9}, {%0,%1,%2,%3};"
        : "+f"(d[0]), "+f"(d[1]), "+f"(d[2]), "+f"(d[3])
        : "r"(a[0]), "r"(a[1]), "r"(a[2]), "r"(a[3]), "r"(b0), "r"(b1));
}

// ===========================================================================
// Kernel 1: fused QKV projection on mma.sync tf32.
// CTA: 128 rows x 192 cols, K=1024 tiled at 32. 256 thr = 8 warps (4M x 2N),
// warp tile 32x96 (2 m16 x 12 n8). Reg-prefetch double buffering.
// Smem strides: A=36 floats (frag bank = 4r+c, conflict-free),
//               B=200 floats (frag bank = 8k+n, conflict-free).
// ===========================================================================
static constexpr int XS_STRIDE = 36;    // floats
static constexpr int WS_STRIDE = 200;   // floats
static constexpr int XS_ELEMS  = 128 * XS_STRIDE;  // per buffer
static constexpr int WS_ELEMS  = 32 * WS_STRIDE;
static constexpr int PROJ_SMEM = 2 * (XS_ELEMS + WS_ELEMS) * 4;  // 88064 B

__global__ __launch_bounds__(256, 1) void proj_mma(
    const float* __restrict__ x,
    const float* __restrict__ Wq,
    const float* __restrict__ Wk,
    const float* __restrict__ Wv)
{
    extern __shared__ float sm[];
    float* xs = sm;                       // 2 x 128 x 36
    float* ws = sm + 2 * XS_ELEMS;        // 2 x 32 x 200

    const int tid  = threadIdx.x;
    const int lane = tid & 31;
    const int wid  = tid >> 5;
    const int m0   = (wid & 3) * 32;      // warp M offset
    const int n0   = (wid >> 2) * 96;     // warp N offset
    const int row0 = blockIdx.x * 128;

    const float* Wm[3] = {Wq, Wk, Wv};

    float acc[2][12][4];
#pragma unroll
    for (int i = 0; i < 2; i++)
#pragma unroll
        for (int j = 0; j < 12; j++)
#pragma unroll
            for (int c = 0; c < 4; c++) acc[i][j][c] = 0.f;

    float4 pa[4], pb[6];

    // --- prefetch helpers (inlined manually) ---
    // A: thread covers (row = tid/8 + 32p, quad = tid%8), float4 each.
    // B: flat f = tid*4 + 1024p, kk=f/192, r=f%192, m=r/64, h=r%63.
    const int ar = tid >> 3, aq = tid & 7;

#define LDG_TILE(KT)                                                          \
    do {                                                                      \
        const int kc = (KT) * 32;                                             \
        _Pragma("unroll")                                                     \
        for (int p = 0; p < 4; p++)                                           \
            pa[p] = *(const float4*)&x[(size_t)(row0 + ar + 32 * p) * CC      \
                                       + kc + aq * 4];                        \
        _Pragma("unroll")                                                     \
        for (int p = 0; p < 6; p++) {                                         \
            int f = tid * 4 + 1024 * p;                                       \
            int kk = f / 192, r = f % 192;                                    \
            int mtx = r >> 6, h = r & 63;                                     \
            pb[p] = *(const float4*)&Wm[mtx][(size_t)(kc + kk) * HSd + h];    \
        }                                                                     \
    } while (0)

#define STS_TILE(BUF)                                                         \
    do {                                                                      \
        float* xb = xs + (BUF) * XS_ELEMS;                                    \
        float* wb = ws + (BUF) * WS_ELEMS;                                    \
        _Pragma("unroll")                                                     \
        for (int p = 0; p < 4; p++) {                                         \
            float4 v = pa[p];                                                 \
            v.x = to_tf32(v.x); v.y = to_tf32(v.y);                           \
            v.z = to_tf32(v.z); v.w = to_tf32(v.w);                           \
            *(float4*)&xb[(ar + 32 * p) * XS_STRIDE + aq * 4] = v;            \
        }                                                                     \
        _Pragma("unroll")                                                     \
        for (int p = 0; p < 6; p++) {                                         \
            int f = tid * 4 + 1024 * p;                                       \
            int kk = f / 192, r = f % 192;                                    \
            float4 v = pb[p];                                                 \
            v.x = to_tf32(v.x); v.y = to_tf32(v.y);                           \
            v.z = to_tf32(v.z); v.w = to_tf32(v.w);                           \
            *(float4*)&wb[kk * WS_STRIDE + r] = v;                            \
        }                                                                     \
    } while (0)

    LDG_TILE(0);
    STS_TILE(0);
    __syncthreads();

    for (int kt = 0; kt < 32; kt++) {
        if (kt < 31) LDG_TILE(kt + 1);

        const float* X = xs + (kt & 1) * XS_ELEMS;
        const float* W = ws + (kt & 1) * WS_ELEMS;

#pragma unroll
        for (int k = 0; k < 4; k++) {
            uint32_t a[2][4];
#pragma unroll
            for (int i = 0; i < 2; i++) {
                int r = m0 + i * 16 + (lane >> 2);
                int c = k * 8 + (lane & 3);
                a[i][0] = __float_as_uint(X[r * XS_STRIDE + c]);
                a[i][1] = __float_as_uint(X[(r + 8) * XS_STRIDE + c]);
                a[i][2] = __float_as_uint(X[r * XS_STRIDE + c + 4]);
                a[i][3] = __float_as_uint(X[(r + 8) * XS_STRIDE + c + 4]);
            }
#pragma unroll
            for (int j = 0; j < 12; j++) {
                int kr = k * 8 + (lane & 3);
                int nc = n0 + j * 8 + (lane >> 2);
                uint32_t b0 = __float_as_uint(W[kr * WS_STRIDE + nc]);
                uint32_t b1 = __float_as_uint(W[(kr + 4) * WS_STRIDE + nc]);
                mma_t(acc[0][j], a[0], b0, b1);
                mma_t(acc[1][j], a[1], b0, b1);
            }
        }

        if (kt < 31) STS_TILE((kt + 1) & 1);
        __syncthreads();
    }

    // epilogue: D frag (c0,c1)=(row, 2q),(row, 2q+1); (c2,c3)=row+8
#pragma unroll
    for (int i = 0; i < 2; i++) {
        int row = row0 + m0 + i * 16 + (lane >> 2);
#pragma unroll
        for (int j = 0; j < 12; j++) {
            int n   = n0 + j * 8 + 2 * (lane & 3);
            int mtx = n >> 6, h = n & 63;
            float* dst = (mtx == 0) ? g_q : ((mtx == 1) ? g_k : g_v);
            *(float2*)&dst[(size_t)row * HSd + h] =
                make_float2(acc[i][j][0], acc[i][j][1]);
            *(float2*)&dst[(size_t)(row + 8) * HSd + h] =
                make_float2(acc[i][j][2], acc[i][j][3]);
        }
    }
#undef LDG_TILE
#undef STS_TILE
}

// ===========================================================================
// Kernel 2: causal flash attention on mma.sync tf32.
// CTA: Q-tile 128 rows, KV-tile 64. 8 warps, each owns one m16 row band and
// the full N=64 — softmax reductions are quad-shuffles only (no cross-warp).
// All smem arrays stride 68 floats: every fragment access pattern maps to
// bank (4r + c) with r in 0..7, c in 0..3 -> conflict-free.
// ===========================================================================
static constexpr int AST = 68;  // smem stride (floats)
static constexpr int ATTN_SMEM = (128 + 64 + 64 + 128) * AST * 4;  // 104448 B

__global__ __launch_bounds__(256, 1) void attn_mma(float* __restrict__ out)
{
    extern __shared__ float sm[];
    float* Qs = sm;                    // 128 x 68
    float* Ks = Qs + 128 * AST;        // 64 x 68
    float* Vs = Ks + 64 * AST;         // 64 x 68
    float* Ps = Vs + 64 * AST;         // 128 x 68

    const int tid  = threadIdx.x;
    const int lane = tid & 31;
    const int wid  = tid >> 5;
    const int b    = blockIdx.x;
    const int qtile = (gridDim.y - 1) - blockIdx.y;   // heavy tiles first
    const int qr0  = qtile * 128;
    const size_t base = (size_t)b * TT * HSd;

    // load Q tile (tf32-rounded)
#pragma unroll
    for (int p = 0; p < 8; p++) {
        int f = tid * 4 + 1024 * p;
        int r = f >> 6, c = f & 63;
        float4 v = *(const float4*)&g_q[base + (size_t)(qr0 + r) * HSd + c];
        v.x = to_tf32(v.x); v.y = to_tf32(v.y);
        v.z = to_tf32(v.z); v.w = to_tf32(v.w);
        *(float4*)&Qs[r * AST + c] = v;
    }

    float o[8][4];
    float m0s = -1e30f, m1s = -1e30f, l0s = 0.f, l1s = 0.f;
#pragma unroll
    for (int j = 0; j < 8; j++)
#pragma unroll
        for (int c = 0; c < 4; c++) o[j][c] = 0.f;

    const int rlow = qr0 + wid * 16 + (lane >> 2);  // global row (and +8)
    const int nkt  = qtile * 2 + 2;

    for (int kt = 0; kt < nkt; kt++) {
        __syncthreads();
#pragma unroll
        for (int p = 0; p < 4; p++) {
            int f = tid * 4 + 1024 * p;
            int r = f >> 6, c = f & 63;
            float4 kv = *(const float4*)&g_k[base + (size_t)(kt * 64 + r) * HSd + c];
            kv.x = to_tf32(kv.x); kv.y = to_tf32(kv.y);
            kv.z = to_tf32(kv.z); kv.w = to_tf32(kv.w);
            *(float4*)&Ks[r * AST + c] = kv;
            float4 vv = *(const float4*)&g_v[base + (size_t)(kt * 64 + r) * HSd + c];
            vv.x = to_tf32(vv.x); vv.y = to_tf32(vv.y);
            vv.z = to_tf32(vv.z); vv.w = to_tf32(vv.w);
            *(float4*)&Vs[r * AST + c] = vv;
        }
        __syncthreads();

        // warp-uniform skip of fully-masked KV tiles
        if (kt * 64 > qr0 + wid * 16 + 15) continue;

        // ---- S = Q K^T ----
        float s[8][4];
#pragma unroll
        for (int j = 0; j < 8; j++)
#pragma unroll
            for (int c = 0; c < 4; c++) s[j][c] = 0.f;

#pragma unroll
        for (int k = 0; k < 8; k++) {
            uint32_t a[4];
            int r = wid * 16 + (lane >> 2);
            int c = k * 8 + (lane & 3);
            a[0] = __float_as_uint(Qs[r * AST + c]);
            a[1] = __float_as_uint(Qs[(r + 8) * AST + c]);
            a[2] = __float_as_uint(Qs[r * AST + c + 4]);
            a[3] = __float_as_uint(Qs[(r + 8) * AST + c + 4]);
#pragma unroll
            for (int j = 0; j < 8; j++) {
                int key = j * 8 + (lane >> 2);
                uint32_t b0 = __float_as_uint(Ks[key * AST + c]);
                uint32_t b1 = __float_as_uint(Ks[key * AST + c + 4]);
                mma_t(s[j], a, b0, b1);
            }
        }

        // ---- scale + causal mask ----
#pragma unroll
        for (int j = 0; j < 8; j++) {
            int col = kt * 64 + j * 8 + 2 * (lane & 3);
            s[j][0] = (col     > rlow    ) ? -1e30f : s[j][0] * 0.03125f;
            s[j][1] = (col + 1 > rlow    ) ? -1e30f : s[j][1] * 0.03125f;
            s[j][2] = (col     > rlow + 8) ? -1e30f : s[j][2] * 0.03125f;
            s[j][3] = (col + 1 > rlow + 8) ? -1e30f : s[j][3] * 0.03125f;
        }

        // ---- online softmax (quad reductions) ----
        float mx0 = -1e30f, mx1 = -1e30f;
#pragma unroll
        for (int j = 0; j < 8; j++) {
            mx0 = fmaxf(mx0, fmaxf(s[j][0], s[j][1]));
            mx1 = fmaxf(mx1, fmaxf(s[j][2], s[j][3]));
        }
#pragma unroll
        for (int off = 1; off <= 2; off <<= 1) {
            mx0 = fmaxf(mx0, __shfl_xor_sync(0xffffffffu, mx0, off));
            mx1 = fmaxf(mx1, __shfl_xor_sync(0xffffffffu, mx1, off));
        }
        float mn0 = fmaxf(m0s, mx0), mn1 = fmaxf(m1s, mx1);
        float c0 = __expf(m0s - mn0), c1 = __expf(m1s - mn1);
        m0s = mn0; m1s = mn1;

        float rs0 = 0.f, rs1 = 0.f;
#pragma unroll
        for (int j = 0; j < 8; j++) {
            s[j][0] = __expf(s[j][0] - mn0);
            s[j][1] = __expf(s[j][1] - mn0);
            s[j][2] = __expf(s[j][2] - mn1);
            s[j][3] = __expf(s[j][3] - mn1);
            rs0 += s[j][0] + s[j][1];
            rs1 += s[j][2] + s[j][3];
        }
#pragma unroll
        for (int off = 1; off <= 2; off <<= 1) {
            rs0 += __shfl_xor_sync(0xffffffffu, rs0, off);
            rs1 += __shfl_xor_sync(0xffffffffu, rs1, off);
        }
        l0s = l0s * c0 + rs0;
        l1s = l1s * c1 + rs1;
#pragma unroll
        for (int j = 0; j < 8; j++) {
            o[j][0] *= c0; o[j][1] *= c0;
            o[j][2] *= c1; o[j][3] *= c1;
        }

        // ---- stage P (own rows only -> warp-local ordering) ----
        {
            int r = wid * 16 + (lane >> 2);
            int cc = 2 * (lane & 3);
#pragma unroll
            for (int j = 0; j < 8; j++) {
                *(float2*)&Ps[r * AST + j * 8 + cc] =
                    make_float2(to_tf32(s[j][0]), to_tf32(s[j][1]));
                *(float2*)&Ps[(r + 8) * AST + j * 8 + cc] =
                    make_float2(to_tf32(s[j][2]), to_tf32(s[j][3]));
            }
        }
        __syncwarp();

        // ---- O += P V ----
#pragma unroll
        for (int k = 0; k < 8; k++) {
            uint32_t a[4];
            int r = wid * 16 + (lane >> 2);
            int c = k * 8 + (lane & 3);
            a[0] = __float_as_uint(Ps[r * AST + c]);
            a[1] = __float_as_uint(Ps[(r + 8) * AST + c]);
            a[2] = __float_as_uint(Ps[r * AST + c + 4]);
            a[3] = __float_as_uint(Ps[(r + 8) * AST + c + 4]);
#pragma unroll
            for (int j = 0; j < 8; j++) {
                int sv = k * 8 + (lane & 3);
                int h  = j * 8 + (lane >> 2);
                uint32_t b0 = __float_as_uint(Vs[sv * AST + h]);
                uint32_t b1 = __float_as_uint(Vs[(sv + 4) * AST + h]);
                mma_t(o[j], a, b0, b1);
            }
        }
    }

    // epilogue
    float inv0 = 1.0f / l0s, inv1 = 1.0f / l1s;
#pragma unroll
    for (int j = 0; j < 8; j++) {
        int col = j * 8 + 2 * (lane & 3);
        *(float2*)&out[base + (size_t)rlow * HSd + col] =
            make_float2(o[j][0] * inv0, o[j][1] * inv0);
        *(float2*)&out[base + (size_t)(rlow + 8) * HSd + col] =
            make_float2(o[j][2] * inv1, o[j][3] * inv1);
    }
}

// ===========================================================================
// Launch. Inputs: x, mask, Wq, Wk, Wv (mask applied analytically).
// ===========================================================================
extern "C" void kernel_launch(void* const* d_in, const int* in_sizes, int n_in,
                              void* d_out, int out_size)
{
    const float* x  = (const float*)d_in[0];
    const float* Wq = (const float*)d_in[2];
    const float* Wk = (const float*)d_in[3];
    const float* Wv = (const float*)d_in[4];
    float* out = (float*)d_out;

    static bool attr_set = false;
    if (!attr_set) {
        cudaFuncSetAttribute(proj_mma,
                             cudaFuncAttributeMaxDynamicSharedMemorySize, PROJ_SMEM);
        cudaFuncSetAttribute(attn_mma,
                             cudaFuncAttributeMaxDynamicSharedMemorySize, ATTN_SMEM);
        attr_set = true;
    }

    proj_mma<<<(BB * TT) / 128, 256, PROJ_SMEM>>>(x, Wq, Wk, Wv);
    attn_mma<<<dim3(BB, TT / 128), 256, ATTN_SMEM>>>(out);
}

// round 14
// speedup vs baseline: 4.6032x; 1.0024x over previous
#include <cuda_runtime.h>
#include <cstdint>
#include <math.h>

static constexpr int BB = 8;
static constexpr int TT = 2048;
static constexpr int CC = 1024;
static constexpr int HSd = 64;

// fp32 scratch for q,k,v (12 MB; __device__ globals, no allocation)
__device__ float g_q[BB * TT * HSd];
__device__ float g_k[BB * TT * HSd];
__device__ float g_v[BB * TT * HSd];

__device__ __forceinline__ float to_tf32(float x) {
    float r;
    asm("cvt.rna.tf32.f32 %0, %1;" : "=f"(r) : "f"(x));
    return r;
}

// mma.sync m16n8k8 tf32: D += A(16x8,row) * B(8x8,col). D/C in-place.
__device__ __forceinline__ void mma_t(float* d, const uint32_t* a,
                                      uint32_t b0, uint32_t b1) {
    asm volatile(
        "mma.sync.aligned.m16n8k8.row.col.f32.tf32.tf32.f32 "
        "{%0,%1,%2,%3}, {%4,%5,%6,%7}, {%8,%9}, {%0,%1,%2,%3};"
        : "+f"(d[0]), "+f"(d[1]), "+f"(d[2]), "+f"(d[3])
        : "r"(a[0]), "r"(a[1]), "r"(a[2]), "r"(a[3]), "r"(b0), "r"(b1));
}

// ===========================================================================
// Kernel 1: fused QKV projection on mma.sync tf32.
// CTA: 128 rows x 192 cols, K=1024 tiled at 32. 256 thr = 8 warps (4M x 2N),
// warp tile 32x96 (2 m16 x 12 n8). Reg-prefetch double buffering.
// Smem strides: A=36 floats (frag bank = 4r+c, conflict-free),
//               B=200 floats (frag bank = 8k+n, conflict-free).
// ===========================================================================
static constexpr int XS_STRIDE = 36;    // floats
static constexpr int WS_STRIDE = 200;   // floats
static constexpr int XS_ELEMS  = 128 * XS_STRIDE;  // per buffer
static constexpr int WS_ELEMS  = 32 * WS_STRIDE;
static constexpr int PROJ_SMEM = 2 * (XS_ELEMS + WS_ELEMS) * 4;  // 88064 B

__global__ __launch_bounds__(256, 1) void proj_mma(
    const float* __restrict__ x,
    const float* __restrict__ Wq,
    const float* __restrict__ Wk,
    const float* __restrict__ Wv)
{
    extern __shared__ float sm[];
    float* xs = sm;                       // 2 x 128 x 36
    float* ws = sm + 2 * XS_ELEMS;        // 2 x 32 x 200

    const int tid  = threadIdx.x;
    const int lane = tid & 31;
    const int wid  = tid >> 5;
    const int m0   = (wid & 3) * 32;      // warp M offset
    const int n0   = (wid >> 2) * 96;     // warp N offset
    const int row0 = blockIdx.x * 128;

    const float* Wm[3] = {Wq, Wk, Wv};

    float acc[2][12][4];
#pragma unroll
    for (int i = 0; i < 2; i++)
#pragma unroll
        for (int j = 0; j < 12; j++)
#pragma unroll
            for (int c = 0; c < 4; c++) acc[i][j][c] = 0.f;

    float4 pa[4], pb[6];

    // --- prefetch helpers (inlined manually) ---
    // A: thread covers (row = tid/8 + 32p, quad = tid%8), float4 each.
    // B: flat f = tid*4 + 1024p, kk=f/192, r=f%192, m=r/64, h=r%63.
    const int ar = tid >> 3, aq = tid & 7;

#define LDG_TILE(KT)                                                          \
    do {                                                                      \
        const int kc = (KT) * 32;                                             \
        _Pragma("unroll")                                                     \
        for (int p = 0; p < 4; p++)                                           \
            pa[p] = *(const float4*)&x[(size_t)(row0 + ar + 32 * p) * CC      \
                                       + kc + aq * 4];                        \
        _Pragma("unroll")                                                     \
        for (int p = 0; p < 6; p++) {                                         \
            int f = tid * 4 + 1024 * p;                                       \
            int kk = f / 192, r = f % 192;                                    \
            int mtx = r >> 6, h = r & 63;                                     \
            pb[p] = *(const float4*)&Wm[mtx][(size_t)(kc + kk) * HSd + h];    \
        }                                                                     \
    } while (0)

#define STS_TILE(BUF)                                                         \
    do {                                                                      \
        float* xb = xs + (BUF) * XS_ELEMS;                                    \
        float* wb = ws + (BUF) * WS_ELEMS;                                    \
        _Pragma("unroll")                                                     \
        for (int p = 0; p < 4; p++) {                                         \
            float4 v = pa[p];                                                 \
            v.x = to_tf32(v.x); v.y = to_tf32(v.y);                           \
            v.z = to_tf32(v.z); v.w = to_tf32(v.w);                           \
            *(float4*)&xb[(ar + 32 * p) * XS_STRIDE + aq * 4] = v;            \
        }                                                                     \
        _Pragma("unroll")                                                     \
        for (int p = 0; p < 6; p++) {                                         \
            int f = tid * 4 + 1024 * p;                                       \
            int kk = f / 192, r = f % 192;                                    \
            float4 v = pb[p];                                                 \
            v.x = to_tf32(v.x); v.y = to_tf32(v.y);                           \
            v.z = to_tf32(v.z); v.w = to_tf32(v.w);                           \
            *(float4*)&wb[kk * WS_STRIDE + r] = v;                            \
        }                                                                     \
    } while (0)

    LDG_TILE(0);
    STS_TILE(0);
    __syncthreads();

    for (int kt = 0; kt < 32; kt++) {
        if (kt < 31) LDG_TILE(kt + 1);

        const float* X = xs + (kt & 1) * XS_ELEMS;
        const float* W = ws + (kt & 1) * WS_ELEMS;

#pragma unroll
        for (int k = 0; k < 4; k++) {
            uint32_t a[2][4];
#pragma unroll
            for (int i = 0; i < 2; i++) {
                int r = m0 + i * 16 + (lane >> 2);
                int c = k * 8 + (lane & 3);
                a[i][0] = __float_as_uint(X[r * XS_STRIDE + c]);
                a[i][1] = __float_as_uint(X[(r + 8) * XS_STRIDE + c]);
                a[i][2] = __float_as_uint(X[r * XS_STRIDE + c + 4]);
                a[i][3] = __float_as_uint(X[(r + 8) * XS_STRIDE + c + 4]);
            }
#pragma unroll
            for (int j = 0; j < 12; j++) {
                int kr = k * 8 + (lane & 3);
                int nc = n0 + j * 8 + (lane >> 2);
                uint32_t b0 = __float_as_uint(W[kr * WS_STRIDE + nc]);
                uint32_t b1 = __float_as_uint(W[(kr + 4) * WS_STRIDE + nc]);
                mma_t(acc[0][j], a[0], b0, b1);
                mma_t(acc[1][j], a[1], b0, b1);
            }
        }

        if (kt < 31) STS_TILE((kt + 1) & 1);
        __syncthreads();
    }

    // epilogue: D frag (c0,c1)=(row, 2q),(row, 2q+1); (c2,c3)=row+8
#pragma unroll
    for (int i = 0; i < 2; i++) {
        int row = row0 + m0 + i * 16 + (lane >> 2);
#pragma unroll
        for (int j = 0; j < 12; j++) {
            int n   = n0 + j * 8 + 2 * (lane & 3);
            int mtx = n >> 6, h = n & 63;
            float* dst = (mtx == 0) ? g_q : ((mtx == 1) ? g_k : g_v);
            *(float2*)&dst[(size_t)row * HSd + h] =
                make_float2(acc[i][j][0], acc[i][j][1]);
            *(float2*)&dst[(size_t)(row + 8) * HSd + h] =
                make_float2(acc[i][j][2], acc[i][j][3]);
        }
    }
#undef LDG_TILE
#undef STS_TILE
}

// ===========================================================================
// Kernel 2: causal flash attention on mma.sync tf32.
// CTA: Q-tile 128 rows, KV-tile 64. 8 warps, each owns one m16 row band and
// the full N=64 — softmax reductions are quad-shuffles only (no cross-warp).
// All smem arrays stride 68 floats: every fragment access pattern maps to
// bank (4r + c) with r in 0..7, c in 0..3 -> conflict-free.
// ===========================================================================
static constexpr int AST = 68;  // smem stride (floats)
static constexpr int ATTN_SMEM = (128 + 64 + 64 + 128) * AST * 4;  // 104448 B

__global__ __launch_bounds__(256, 1) void attn_mma(float* __restrict__ out)
{
    extern __shared__ float sm[];
    float* Qs = sm;                    // 128 x 68
    float* Ks = Qs + 128 * AST;        // 64 x 68
    float* Vs = Ks + 64 * AST;         // 64 x 68
    float* Ps = Vs + 64 * AST;         // 128 x 68

    const int tid  = threadIdx.x;
    const int lane = tid & 31;
    const int wid  = tid >> 5;
    const int b    = blockIdx.x;
    const int qtile = (gridDim.y - 1) - blockIdx.y;   // heavy tiles first
    const int qr0  = qtile * 128;
    const size_t base = (size_t)b * TT * HSd;

    // load Q tile (tf32-rounded)
#pragma unroll
    for (int p = 0; p < 8; p++) {
        int f = tid * 4 + 1024 * p;
        int r = f >> 6, c = f & 63;
        float4 v = *(const float4*)&g_q[base + (size_t)(qr0 + r) * HSd + c];
        v.x = to_tf32(v.x); v.y = to_tf32(v.y);
        v.z = to_tf32(v.z); v.w = to_tf32(v.w);
        *(float4*)&Qs[r * AST + c] = v;
    }

    float o[8][4];
    float m0s = -1e30f, m1s = -1e30f, l0s = 0.f, l1s = 0.f;
#pragma unroll
    for (int j = 0; j < 8; j++)
#pragma unroll
        for (int c = 0; c < 4; c++) o[j][c] = 0.f;

    const int rlow = qr0 + wid * 16 + (lane >> 2);  // global row (and +8)
    const int nkt  = qtile * 2 + 2;

    for (int kt = 0; kt < nkt; kt++) {
        __syncthreads();
#pragma unroll
        for (int p = 0; p < 4; p++) {
            int f = tid * 4 + 1024 * p;
            int r = f >> 6, c = f & 63;
            float4 kv = *(const float4*)&g_k[base + (size_t)(kt * 64 + r) * HSd + c];
            kv.x = to_tf32(kv.x); kv.y = to_tf32(kv.y);
            kv.z = to_tf32(kv.z); kv.w = to_tf32(kv.w);
            *(float4*)&Ks[r * AST + c] = kv;
            float4 vv = *(const float4*)&g_v[base + (size_t)(kt * 64 + r) * HSd + c];
            vv.x = to_tf32(vv.x); vv.y = to_tf32(vv.y);
            vv.z = to_tf32(vv.z); vv.w = to_tf32(vv.w);
            *(float4*)&Vs[r * AST + c] = vv;
        }
        __syncthreads();

        // warp-uniform skip of fully-masked KV tiles
        if (kt * 64 > qr0 + wid * 16 + 15) continue;

        // ---- S = Q K^T ----
        float s[8][4];
#pragma unroll
        for (int j = 0; j < 8; j++)
#pragma unroll
            for (int c = 0; c < 4; c++) s[j][c] = 0.f;

#pragma unroll
        for (int k = 0; k < 8; k++) {
            uint32_t a[4];
            int r = wid * 16 + (lane >> 2);
            int c = k * 8 + (lane & 3);
            a[0] = __float_as_uint(Qs[r * AST + c]);
            a[1] = __float_as_uint(Qs[(r + 8) * AST + c]);
            a[2] = __float_as_uint(Qs[r * AST + c + 4]);
            a[3] = __float_as_uint(Qs[(r + 8) * AST + c + 4]);
#pragma unroll
            for (int j = 0; j < 8; j++) {
                int key = j * 8 + (lane >> 2);
                uint32_t b0 = __float_as_uint(Ks[key * AST + c]);
                uint32_t b1 = __float_as_uint(Ks[key * AST + c + 4]);
                mma_t(s[j], a, b0, b1);
            }
        }

        // ---- scale + causal mask ----
#pragma unroll
        for (int j = 0; j < 8; j++) {
            int col = kt * 64 + j * 8 + 2 * (lane & 3);
            s[j][0] = (col     > rlow    ) ? -1e30f : s[j][0] * 0.03125f;
            s[j][1] = (col + 1 > rlow    ) ? -1e30f : s[j][1] * 0.03125f;
            s[j][2] = (col     > rlow + 8) ? -1e30f : s[j][2] * 0.03125f;
            s[j][3] = (col + 1 > rlow + 8) ? -1e30f : s[j][3] * 0.03125f;
        }

        // ---- online softmax (quad reductions) ----
        float mx0 = -1e30f, mx1 = -1e30f;
#pragma unroll
        for (int j = 0; j < 8; j++) {
            mx0 = fmaxf(mx0, fmaxf(s[j][0], s[j][1]));
            mx1 = fmaxf(mx1, fmaxf(s[j][2], s[j][3]));
        }
#pragma unroll
        for (int off = 1; off <= 2; off <<= 1) {
            mx0 = fmaxf(mx0, __shfl_xor_sync(0xffffffffu, mx0, off));
            mx1 = fmaxf(mx1, __shfl_xor_sync(0xffffffffu, mx1, off));
        }
        float mn0 = fmaxf(m0s, mx0), mn1 = fmaxf(m1s, mx1);
        float c0 = __expf(m0s - mn0), c1 = __expf(m1s - mn1);
        m0s = mn0; m1s = mn1;

        float rs0 = 0.f, rs1 = 0.f;
#pragma unroll
        for (int j = 0; j < 8; j++) {
            s[j][0] = __expf(s[j][0] - mn0);
            s[j][1] = __expf(s[j][1] - mn0);
            s[j][2] = __expf(s[j][2] - mn1);
            s[j][3] = __expf(s[j][3] - mn1);
            rs0 += s[j][0] + s[j][1];
            rs1 += s[j][2] + s[j][3];
        }
#pragma unroll
        for (int off = 1; off <= 2; off <<= 1) {
            rs0 += __shfl_xor_sync(0xffffffffu, rs0, off);
            rs1 += __shfl_xor_sync(0xffffffffu, rs1, off);
        }
        l0s = l0s * c0 + rs0;
        l1s = l1s * c1 + rs1;
#pragma unroll
        for (int j = 0; j < 8; j++) {
            o[j][0] *= c0; o[j][1] *= c0;
            o[j][2] *= c1; o[j][3] *= c1;
        }

        // ---- stage P (own rows only -> warp-local ordering) ----
        {
            int r = wid * 16 + (lane >> 2);
            int cc = 2 * (lane & 3);
#pragma unroll
            for (int j = 0; j < 8; j++) {
                *(float2*)&Ps[r * AST + j * 8 + cc] =
                    make_float2(to_tf32(s[j][0]), to_tf32(s[j][1]));
                *(float2*)&Ps[(r + 8) * AST + j * 8 + cc] =
                    make_float2(to_tf32(s[j][2]), to_tf32(s[j][3]));
            }
        }
        __syncwarp();

        // ---- O += P V ----
#pragma unroll
        for (int k = 0; k < 8; k++) {
            uint32_t a[4];
            int r = wid * 16 + (lane >> 2);
            int c = k * 8 + (lane & 3);
            a[0] = __float_as_uint(Ps[r * AST + c]);
            a[1] = __float_as_uint(Ps[(r + 8) * AST + c]);
            a[2] = __float_as_uint(Ps[r * AST + c + 4]);
            a[3] = __float_as_uint(Ps[(r + 8) * AST + c + 4]);
#pragma unroll
            for (int j = 0; j < 8; j++) {
                int sv = k * 8 + (lane & 3);
                int h  = j * 8 + (lane >> 2);
                uint32_t b0 = __float_as_uint(Vs[sv * AST + h]);
                uint32_t b1 = __float_as_uint(Vs[(sv + 4) * AST + h]);
                mma_t(o[j], a, b0, b1);
            }
        }
    }

    // epilogue
    float inv0 = 1.0f / l0s, inv1 = 1.0f / l1s;
#pragma unroll
    for (int j = 0; j < 8; j++) {
        int col = j * 8 + 2 * (lane & 3);
        *(float2*)&out[base + (size_t)rlow * HSd + col] =
            make_float2(o[j][0] * inv0, o[j][1] * inv0);
        *(float2*)&out[base + (size_t)(rlow + 8) * HSd + col] =
            make_float2(o[j][2] * inv1, o[j][3] * inv1);
    }
}

// ===========================================================================
// Launch. Inputs: x, mask, Wq, Wk, Wv (mask applied analytically).
// ===========================================================================
extern "C" void kernel_launch(void* const* d_in, const int* in_sizes, int n_in,
                              void* d_out, int out_size)
{
    const float* x  = (const float*)d_in[0];
    const float* Wq = (const float*)d_in[2];
    const float* Wk = (const float*)d_in[3];
    const float* Wv = (const float*)d_in[4];
    float* out = (float*)d_out;

    static bool attr_set = false;
    if (!attr_set) {
        cudaFuncSetAttribute(proj_mma,
                             cudaFuncAttributeMaxDynamicSharedMemorySize, PROJ_SMEM);
        cudaFuncSetAttribute(attn_mma,
                             cudaFuncAttributeMaxDynamicSharedMemorySize, ATTN_SMEM);
        attr_set = true;
    }

    proj_mma<<<(BB * TT) / 128, 256, PROJ_SMEM>>>(x, Wq, Wk, Wv);
    attn_mma<<<dim3(BB, TT / 128), 256, ATTN_SMEM>>>(out);
}

// round 15
// speedup vs baseline: 5.1829x; 1.1259x over previous
#include <cuda_runtime.h>
#include <cstdint>
#include <math.h>

static constexpr int BB = 8;
static constexpr int TT = 2048;
static constexpr int CC = 1024;
static constexpr int HSd = 64;

// fp32 scratch for q,k,v (12 MB; __device__ globals, no allocation)
__device__ float g_q[BB * TT * HSd];
__device__ float g_k[BB * TT * HSd];
__device__ float g_v[BB * TT * HSd];

__device__ __forceinline__ float to_tf32(float x) {
    float r;
    asm("cvt.rna.tf32.f32 %0, %1;" : "=f"(r) : "f"(x));
    return r;
}

// mma.sync m16n8k8 tf32: D += A(16x8,row) * B(8x8,col). D/C in-place.
__device__ __forceinline__ void mma_t(float* d, const uint32_t* a,
                                      uint32_t b0, uint32_t b1) {
    asm volatile(
        "mma.sync.aligned.m16n8k8.row.col.f32.tf32.tf32.f32 "
        "{%0,%1,%2,%3}, {%4,%5,%6,%7}, {%8,%9}, {%0,%1,%2,%3};"
        : "+f"(d[0]), "+f"(d[1]), "+f"(d[2]), "+f"(d[3])
        : "r"(a[0]), "r"(a[1]), "r"(a[2]), "r"(a[3]), "r"(b0), "r"(b1));
}

// ===========================================================================
// Kernel 1: fused QKV projection on mma.sync tf32.
// 256 CTAs x 256 thr. CTA tile: 64 rows x 192 cols, K=1024 tiled at 32.
// 8 warps as (2M x 4N); warp tile 32x48 (2 m16 x 6 n8). Double buffered.
// Smem strides: A=36 (frag bank 4r+c), B=200 (frag bank 8k+n) — conflict-free.
// 2 CTAs/SM.
// ===========================================================================
static constexpr int XS_STRIDE = 36;
static constexpr int WS_STRIDE = 200;
static constexpr int XS_ELEMS  = 64 * XS_STRIDE;
static constexpr int WS_ELEMS  = 32 * WS_STRIDE;
static constexpr int PROJ_SMEM = 2 * (XS_ELEMS + WS_ELEMS) * 4;  // 69632 B

__global__ __launch_bounds__(256, 2) void proj_mma(
    const float* __restrict__ x,
    const float* __restrict__ Wq,
    const float* __restrict__ Wk,
    const float* __restrict__ Wv)
{
    extern __shared__ float sm[];
    float* xs = sm;                       // 2 x 64 x 36
    float* ws = sm + 2 * XS_ELEMS;        // 2 x 32 x 200

    const int tid  = threadIdx.x;
    const int lane = tid & 31;
    const int wid  = tid >> 5;
    const int m0   = (wid & 1) * 32;      // warp M offset
    const int n0   = (wid >> 1) * 48;     // warp N offset
    const int row0 = blockIdx.x * 64;

    const float* Wm[3] = {Wq, Wk, Wv};

    float acc[2][6][4];
#pragma unroll
    for (int i = 0; i < 2; i++)
#pragma unroll
        for (int j = 0; j < 6; j++)
#pragma unroll
            for (int c = 0; c < 4; c++) acc[i][j][c] = 0.f;

    float4 pa[2], pb[6];
    const int ar = tid >> 3, aq = tid & 7;  // A: 32 rows/pass x 8 quads

#define LDG_TILE(KT)                                                          \
    do {                                                                      \
        const int kc = (KT) * 32;                                             \
        _Pragma("unroll")                                                     \
        for (int p = 0; p < 2; p++)                                           \
            pa[p] = *(const float4*)&x[(size_t)(row0 + ar + 32 * p) * CC      \
                                       + kc + aq * 4];                        \
        _Pragma("unroll")                                                     \
        for (int p = 0; p < 6; p++) {                                         \
            int f = tid * 4 + 1024 * p;                                       \
            int kk = f / 192, r = f % 192;                                    \
            int mtx = r >> 6, h = r & 63;                                     \
            pb[p] = *(const float4*)&Wm[mtx][(size_t)(kc + kk) * HSd + h];    \
        }                                                                     \
    } while (0)

#define STS_TILE(BUF)                                                         \
    do {                                                                      \
        float* xb = xs + (BUF) * XS_ELEMS;                                    \
        float* wb = ws + (BUF) * WS_ELEMS;                                    \
        _Pragma("unroll")                                                     \
        for (int p = 0; p < 2; p++) {                                         \
            float4 v = pa[p];                                                 \
            v.x = to_tf32(v.x); v.y = to_tf32(v.y);                           \
            v.z = to_tf32(v.z); v.w = to_tf32(v.w);                           \
            *(float4*)&xb[(ar + 32 * p) * XS_STRIDE + aq * 4] = v;            \
        }                                                                     \
        _Pragma("unroll")                                                     \
        for (int p = 0; p < 6; p++) {                                         \
            int f = tid * 4 + 1024 * p;                                       \
            int kk = f / 192, r = f % 192;                                    \
            float4 v = pb[p];                                                 \
            v.x = to_tf32(v.x); v.y = to_tf32(v.y);                           \
            v.z = to_tf32(v.z); v.w = to_tf32(v.w);                           \
            *(float4*)&wb[kk * WS_STRIDE + r] = v;                            \
        }                                                                     \
    } while (0)

    LDG_TILE(0);
    STS_TILE(0);
    __syncthreads();

    for (int kt = 0; kt < 32; kt++) {
        if (kt < 31) LDG_TILE(kt + 1);

        const float* X = xs + (kt & 1) * XS_ELEMS;
        const float* W = ws + (kt & 1) * WS_ELEMS;

#pragma unroll
        for (int k = 0; k < 4; k++) {
            uint32_t a[2][4];
#pragma unroll
            for (int i = 0; i < 2; i++) {
                int r = m0 + i * 16 + (lane >> 2);
                int c = k * 8 + (lane & 3);
                a[i][0] = __float_as_uint(X[r * XS_STRIDE + c]);
                a[i][1] = __float_as_uint(X[(r + 8) * XS_STRIDE + c]);
                a[i][2] = __float_as_uint(X[r * XS_STRIDE + c + 4]);
                a[i][3] = __float_as_uint(X[(r + 8) * XS_STRIDE + c + 4]);
            }
#pragma unroll
            for (int j = 0; j < 6; j++) {
                int kr = k * 8 + (lane & 3);
                int nc = n0 + j * 8 + (lane >> 2);
                uint32_t b0 = __float_as_uint(W[kr * WS_STRIDE + nc]);
                uint32_t b1 = __float_as_uint(W[(kr + 4) * WS_STRIDE + nc]);
                mma_t(acc[0][j], a[0], b0, b1);
                mma_t(acc[1][j], a[1], b0, b1);
            }
        }

        if (kt < 31) STS_TILE((kt + 1) & 1);
        __syncthreads();
    }

#pragma unroll
    for (int i = 0; i < 2; i++) {
        int row = row0 + m0 + i * 16 + (lane >> 2);
#pragma unroll
        for (int j = 0; j < 6; j++) {
            int n   = n0 + j * 8 + 2 * (lane & 3);
            int mtx = n >> 6, h = n & 63;
            float* dst = (mtx == 0) ? g_q : ((mtx == 1) ? g_k : g_v);
            *(float2*)&dst[(size_t)row * HSd + h] =
                make_float2(acc[i][j][0], acc[i][j][1]);
            *(float2*)&dst[(size_t)(row + 8) * HSd + h] =
                make_float2(acc[i][j][2], acc[i][j][3]);
        }
    }
#undef LDG_TILE
#undef STS_TILE
}

// ===========================================================================
// Kernel 2: causal flash attention on mma.sync tf32.
// CTA: Q-tile 64 rows, KV-tile 64; 4 warps (128 thr), each owns one m16 band
// and the full N=64 -> softmax is quad-shuffles only. 3 CTAs/SM (12 warps).
// 256 CTAs; qtile map y<16 ? 31-2y : 2(y-16) balances co-resident pairs.
// All smem arrays stride 68: fragment bank = 4r+c -> conflict-free.
// ===========================================================================
static constexpr int AST = 68;
static constexpr int ATTN_SMEM = (64 * 4) * AST * 4;  // 69632 B

__global__ __launch_bounds__(128, 3) void attn_mma(float* __restrict__ out)
{
    extern __shared__ float sm[];
    float* Qs = sm;                    // 64 x 68
    float* Ks = Qs + 64 * AST;         // 64 x 68
    float* Vs = Ks + 64 * AST;         // 64 x 68
    float* Ps = Vs + 64 * AST;         // 64 x 68

    const int tid  = threadIdx.x;
    const int lane = tid & 31;
    const int wid  = tid >> 5;          // 0..3
    const int b    = blockIdx.x;
    const int y    = blockIdx.y;        // 0..31
    const int qtile = (y < 16) ? (31 - 2 * y) : (2 * (y - 16));
    const int qr0  = qtile * 64;
    const size_t base = (size_t)b * TT * HSd;

    // load Q tile (tf32-rounded): 64x64, 8 float4/thread
#pragma unroll
    for (int p = 0; p < 8; p++) {
        int f = tid * 4 + 512 * p;
        int r = f >> 6, c = f & 63;
        float4 v = *(const float4*)&g_q[base + (size_t)(qr0 + r) * HSd + c];
        v.x = to_tf32(v.x); v.y = to_tf32(v.y);
        v.z = to_tf32(v.z); v.w = to_tf32(v.w);
        *(float4*)&Qs[r * AST + c] = v;
    }

    float o[8][4];
    float m0s = -1e30f, m1s = -1e30f, l0s = 0.f, l1s = 0.f;
#pragma unroll
    for (int j = 0; j < 8; j++)
#pragma unroll
        for (int c = 0; c < 4; c++) o[j][c] = 0.f;

    const int rlow = qr0 + wid * 16 + (lane >> 2);  // global row (and +8)
    const int nkt  = qtile + 1;

    for (int kt = 0; kt < nkt; kt++) {
        __syncthreads();
#pragma unroll
        for (int p = 0; p < 8; p++) {
            int f = tid * 4 + 512 * p;
            int r = f >> 6, c = f & 63;
            float4 kv = *(const float4*)&g_k[base + (size_t)(kt * 64 + r) * HSd + c];
            kv.x = to_tf32(kv.x); kv.y = to_tf32(kv.y);
            kv.z = to_tf32(kv.z); kv.w = to_tf32(kv.w);
            *(float4*)&Ks[r * AST + c] = kv;
            float4 vv = *(const float4*)&g_v[base + (size_t)(kt * 64 + r) * HSd + c];
            vv.x = to_tf32(vv.x); vv.y = to_tf32(vv.y);
            vv.z = to_tf32(vv.z); vv.w = to_tf32(vv.w);
            *(float4*)&Vs[r * AST + c] = vv;
        }
        __syncthreads();

        // ---- S = Q K^T ----
        float s[8][4];
#pragma unroll
        for (int j = 0; j < 8; j++)
#pragma unroll
            for (int c = 0; c < 4; c++) s[j][c] = 0.f;

#pragma unroll
        for (int k = 0; k < 8; k++) {
            uint32_t a[4];
            int r = wid * 16 + (lane >> 2);
            int c = k * 8 + (lane & 3);
            a[0] = __float_as_uint(Qs[r * AST + c]);
            a[1] = __float_as_uint(Qs[(r + 8) * AST + c]);
            a[2] = __float_as_uint(Qs[r * AST + c + 4]);
            a[3] = __float_as_uint(Qs[(r + 8) * AST + c + 4]);
#pragma unroll
            for (int j = 0; j < 8; j++) {
                int key = j * 8 + (lane >> 2);
                uint32_t b0 = __float_as_uint(Ks[key * AST + c]);
                uint32_t b1 = __float_as_uint(Ks[key * AST + c + 4]);
                mma_t(s[j], a, b0, b1);
            }
        }

        // ---- scale + causal mask ----
#pragma unroll
        for (int j = 0; j < 8; j++) {
            int col = kt * 64 + j * 8 + 2 * (lane & 3);
            s[j][0] = (col     > rlow    ) ? -1e30f : s[j][0] * 0.03125f;
            s[j][1] = (col + 1 > rlow    ) ? -1e30f : s[j][1] * 0.03125f;
            s[j][2] = (col     > rlow + 8) ? -1e30f : s[j][2] * 0.03125f;
            s[j][3] = (col + 1 > rlow + 8) ? -1e30f : s[j][3] * 0.03125f;
        }

        // ---- online softmax (quad reductions) ----
        float mx0 = -1e30f, mx1 = -1e30f;
#pragma unroll
        for (int j = 0; j < 8; j++) {
            mx0 = fmaxf(mx0, fmaxf(s[j][0], s[j][1]));
            mx1 = fmaxf(mx1, fmaxf(s[j][2], s[j][3]));
        }
#pragma unroll
        for (int off = 1; off <= 2; off <<= 1) {
            mx0 = fmaxf(mx0, __shfl_xor_sync(0xffffffffu, mx0, off));
            mx1 = fmaxf(mx1, __shfl_xor_sync(0xffffffffu, mx1, off));
        }
        float mn0 = fmaxf(m0s, mx0), mn1 = fmaxf(m1s, mx1);
        float c0 = __expf(m0s - mn0), c1 = __expf(m1s - mn1);
        m0s = mn0; m1s = mn1;

        float rs0 = 0.f, rs1 = 0.f;
#pragma unroll
        for (int j = 0; j < 8; j++) {
            s[j][0] = __expf(s[j][0] - mn0);
            s[j][1] = __expf(s[j][1] - mn0);
            s[j][2] = __expf(s[j][2] - mn1);
            s[j][3] = __expf(s[j][3] - mn1);
            rs0 += s[j][0] + s[j][1];
            rs1 += s[j][2] + s[j][3];
        }
#pragma unroll
        for (int off = 1; off <= 2; off <<= 1) {
            rs0 += __shfl_xor_sync(0xffffffffu, rs0, off);
            rs1 += __shfl_xor_sync(0xffffffffu, rs1, off);
        }
        l0s = l0s * c0 + rs0;
        l1s = l1s * c1 + rs1;
#pragma unroll
        for (int j = 0; j < 8; j++) {
            o[j][0] *= c0; o[j][1] *= c0;
            o[j][2] *= c1; o[j][3] *= c1;
        }

        // ---- stage P (own rows only -> warp-local ordering) ----
        {
            int r = wid * 16 + (lane >> 2);
            int cc = 2 * (lane & 3);
#pragma unroll
            for (int j = 0; j < 8; j++) {
                *(float2*)&Ps[r * AST + j * 8 + cc] =
                    make_float2(to_tf32(s[j][0]), to_tf32(s[j][1]));
                *(float2*)&Ps[(r + 8) * AST + j * 8 + cc] =
                    make_float2(to_tf32(s[j][2]), to_tf32(s[j][3]));
            }
        }
        __syncwarp();

        // ---- O += P V ----
#pragma unroll
        for (int k = 0; k < 8; k++) {
            uint32_t a[4];
            int r = wid * 16 + (lane >> 2);
            int c = k * 8 + (lane & 3);
            a[0] = __float_as_uint(Ps[r * AST + c]);
            a[1] = __float_as_uint(Ps[(r + 8) * AST + c]);
            a[2] = __float_as_uint(Ps[r * AST + c + 4]);
            a[3] = __float_as_uint(Ps[(r + 8) * AST + c + 4]);
#pragma unroll
            for (int j = 0; j < 8; j++) {
                int sv = k * 8 + (lane & 3);
                int h  = j * 8 + (lane >> 2);
                uint32_t b0 = __float_as_uint(Vs[sv * AST + h]);
                uint32_t b1 = __float_as_uint(Vs[(sv + 4) * AST + h]);
                mma_t(o[j], a, b0, b1);
            }
        }
    }

    // epilogue
    float inv0 = 1.0f / l0s, inv1 = 1.0f / l1s;
#pragma unroll
    for (int j = 0; j < 8; j++) {
        int col = j * 8 + 2 * (lane & 3);
        *(float2*)&out[base + (size_t)rlow * HSd + col] =
            make_float2(o[j][0] * inv0, o[j][1] * inv0);
        *(float2*)&out[base + (size_t)(rlow + 8) * HSd + col] =
            make_float2(o[j][2] * inv1, o[j][3] * inv1);
    }
}

// ===========================================================================
// Launch. Inputs: x, mask, Wq, Wk, Wv (mask applied analytically).
// ===========================================================================
extern "C" void kernel_launch(void* const* d_in, const int* in_sizes, int n_in,
                              void* d_out, int out_size)
{
    const float* x  = (const float*)d_in[0];
    const float* Wq = (const float*)d_in[2];
    const float* Wk = (const float*)d_in[3];
    const float* Wv = (const float*)d_in[4];
    float* out = (float*)d_out;

    static bool attr_set = false;
    if (!attr_set) {
        cudaFuncSetAttribute(proj_mma,
                             cudaFuncAttributeMaxDynamicSharedMemorySize, PROJ_SMEM);
        cudaFuncSetAttribute(attn_mma,
                             cudaFuncAttributeMaxDynamicSharedMemorySize, ATTN_SMEM);
        attr_set = true;
    }

    proj_mma<<<(BB * TT) / 64, 256, PROJ_SMEM>>>(x, Wq, Wk, Wv);
    attn_mma<<<dim3(BB, TT / 64), 128, ATTN_SMEM>>>(out);
}